// round 9
// baseline (speedup 1.0000x reference)
#include <cuda_runtime.h>
#include <cuda_bf16.h>
#include <cstdint>

// Problem constants
#define BATCH 4
#define SEQT  2048
#define DMODEL 512
#define NHEAD 8
#define HD    64
#define THREE_D (3 * DMODEL)
#define MROWS (BATCH * SEQT)        // 8192

// Arch-feature dispatch: tcgen05/bulk-async only on *a targets.
#if !defined(__CUDA_ARCH__)
#  define TC_PATH 1
#elif defined(__CUDA_ARCH_HAS_FEATURE__) && \
      (__CUDA_ARCH_HAS_FEATURE__(SM103_ALL) || __CUDA_ARCH_HAS_FEATURE__(SM100_ALL))
#  define TC_PATH 1
#else
#  define TC_PATH 0
#endif

// ---------------------------------------------------------------------------
// Tiled+swizzled bf16 operand layout (SW64):
//   operand with TR-row tiles (TR=256 for GEMM-A, 128 for GEMM-B), K cols.
//   tile (rblk, kblk) is contiguous TR*64 bytes at
//     ((rblk * (K/32) + kblk) * TR * 64)
//   within tile: row r, col c (bf16): bo = r*64 + c*2, swizzled bo^=((bo>>3)&0x30)
// ---------------------------------------------------------------------------

// Scratch (no cudaMalloc allowed)
__device__ float g_qkv[(size_t)MROWS * THREE_D];   // 48 MB fp32
__device__ alignas(128) __nv_bfloat16 g_xh[(size_t)MROWS * DMODEL];
__device__ alignas(128) __nv_bfloat16 g_xl[(size_t)MROWS * DMODEL];
__device__ alignas(128) __nv_bfloat16 g_wih[(size_t)THREE_D * DMODEL];
__device__ alignas(128) __nv_bfloat16 g_wil[(size_t)THREE_D * DMODEL];
__device__ alignas(128) __nv_bfloat16 g_woh[(size_t)DMODEL * DMODEL];
__device__ alignas(128) __nv_bfloat16 g_wol[(size_t)DMODEL * DMODEL];
__device__ alignas(128) __nv_bfloat16 g_atth[(size_t)MROWS * DMODEL];
__device__ alignas(128) __nv_bfloat16 g_attl[(size_t)MROWS * DMODEL];

// ===========================================================================
// Common helpers
// ===========================================================================
__device__ __forceinline__ uint32_t pack_bf16x2(__nv_bfloat16 a, __nv_bfloat16 b) {
    return (uint32_t)__bfloat16_as_ushort(a) |
           ((uint32_t)__bfloat16_as_ushort(b) << 16);
}

__device__ __forceinline__ void split_hilo(float v, __nv_bfloat16& h, __nv_bfloat16& l) {
    h = __float2bfloat16(v);
    l = __float2bfloat16(v - __bfloat162float(h));
}

__device__ __forceinline__ uint32_t sw64(uint32_t bo) {
    return bo ^ ((bo >> 3) & 0x30);
}

// tiled element load (fallback path only)
__device__ __forceinline__ float ld_tiled(
    const __nv_bfloat16* base, int trlog, int row, int col, int Kdim)
{
    int kblk = col >> 5, cin = col & 31;
    int rblk = row >> trlog, rin = row & ((1 << trlog) - 1);
    size_t tile = ((size_t)(rblk * (Kdim >> 5) + kblk)) << (trlog + 6);
    uint32_t bo = sw64((uint32_t)(rin * 64 + cin * 2));
    return __bfloat162float(*(const __nv_bfloat16*)((const char*)base + tile + bo));
}

// ===========================================================================
// fp32 row-major -> tiled+swizzled bf16 hi/lo. One thread = 8 elements.
// ===========================================================================
template<int TRLOG>
__global__ __launch_bounds__(256) void cvt_tiled_kernel(
    const float* __restrict__ src,
    __nv_bfloat16* __restrict__ dh, __nv_bfloat16* __restrict__ dl,
    int R, int Kdim)
{
    int i = blockIdx.x * blockDim.x + threadIdx.x;   // 8-elem granule
    int n8 = (R * Kdim) >> 3;
    if (i >= n8) return;
    const int K8 = Kdim >> 3;
    int row = i / K8;
    int c8  = i - row * K8;

    float4 v0 = __ldg((const float4*)src + i * 2);
    float4 v1 = __ldg((const float4*)src + i * 2 + 1);

    __nv_bfloat16 h0,l0,h1,l1,h2,l2,h3,l3,h4,l4,h5,l5,h6,l6,h7,l7;
    split_hilo(v0.x,h0,l0); split_hilo(v0.y,h1,l1);
    split_hilo(v0.z,h2,l2); split_hilo(v0.w,h3,l3);
    split_hilo(v1.x,h4,l4); split_hilo(v1.y,h5,l5);
    split_hilo(v1.z,h6,l6); split_hilo(v1.w,h7,l7);
    uint4 hi, lo;
    hi.x = pack_bf16x2(h0,h1); hi.y = pack_bf16x2(h2,h3);
    hi.z = pack_bf16x2(h4,h5); hi.w = pack_bf16x2(h6,h7);
    lo.x = pack_bf16x2(l0,l1); lo.y = pack_bf16x2(l2,l3);
    lo.z = pack_bf16x2(l4,l5); lo.w = pack_bf16x2(l6,l7);

    int kblk = c8 >> 2, cc = c8 & 3;
    int rblk = row >> TRLOG, rin = row & ((1 << TRLOG) - 1);
    size_t tile = ((size_t)(rblk * (Kdim >> 5) + kblk)) << (TRLOG + 6);
    uint32_t bo = sw64((uint32_t)(rin * 64 + cc * 16));
    *(uint4*)((char*)dh + tile + bo) = hi;
    *(uint4*)((char*)dl + tile + bo) = lo;
}

// ===========================================================================
// tcgen05 + bulk-async PTX helpers (feature-gated)
// ===========================================================================
#if TC_PATH
__device__ __forceinline__ uint32_t smem_u32(const void* p) {
    uint32_t a;
    asm("{ .reg .u64 t; cvta.to.shared.u64 t, %1; cvt.u32.u64 %0, t; }"
        : "=r"(a) : "l"(p));
    return a;
}

#define TCGEN05_ALLOC(smem_result_addr, nCols) \
    asm volatile( \
        "tcgen05.alloc.cta_group::1.sync.aligned.shared::cta.b32 [%0], %1;" \
        :: "r"((uint32_t)(smem_result_addr)), "r"((uint32_t)(nCols)) : "memory")

#define TCGEN05_DEALLOC(tmem_addr, nCols) \
    asm volatile( \
        "tcgen05.dealloc.cta_group::1.sync.aligned.b32 %0, %1;" \
        :: "r"(tmem_addr), "r"((uint32_t)(nCols)))

#define TCGEN05_RELINQUISH_ALLOC_PERMIT() \
    asm volatile("tcgen05.relinquish_alloc_permit.cta_group::1.sync.aligned;")

#define TCGEN05_COMMIT(mbar_smem_addr) \
    asm volatile( \
        "tcgen05.commit.cta_group::1.mbarrier::arrive::one.shared::cluster.b64 [%0];" \
        :: "r"((uint32_t)(mbar_smem_addr)) : "memory")

#define TCGEN05_FENCE_AFTER() \
    asm volatile("tcgen05.fence::after_thread_sync;" ::: "memory")

#define TCGEN05_WAIT_LD() \
    asm volatile("tcgen05.wait::ld.sync.aligned;" ::: "memory")

#define MBARRIER_INIT(mbar_smem_addr, count) \
    asm volatile( \
        "mbarrier.init.shared.b64 [%0], %1;" \
        :: "r"((uint32_t)(mbar_smem_addr)), "r"((uint32_t)(count)) : "memory")

#define MBARRIER_EXPECT_TX(mbar_smem_addr, tx_bytes) \
    asm volatile( \
        "mbarrier.arrive.expect_tx.shared.b64 _, [%0], %1;" \
        :: "r"((uint32_t)(mbar_smem_addr)), "r"((uint32_t)(tx_bytes)) : "memory")

#define MBARRIER_WAIT_PARITY(mbar_smem_addr, phase_parity) do { \
    uint32_t _mbar = (uint32_t)(mbar_smem_addr); \
    uint32_t _parity = (uint32_t)(phase_parity); \
    uint32_t _done; \
    asm volatile( \
        "{\n\t.reg .pred p;\n\t" \
        "mbarrier.try_wait.parity.acquire.cta.shared::cta.b64 p, [%1], %2;\n\t" \
        "selp.b32 %0, 1, 0, p;\n\t}" \
        : "=r"(_done) : "r"(_mbar), "r"(_parity) : "memory"); \
    if (!_done) { \
        asm volatile( \
            "{\n\t.reg .pred P1;\n\t" \
            "WAIT_LOOP_%=:\n\t" \
            "mbarrier.try_wait.parity.acquire.cta.shared::cta.b64 P1, [%0], %1, 0x989680;\n\t" \
            "@P1 bra.uni WAIT_DONE_%=;\n\t" \
            "bra.uni WAIT_LOOP_%=;\n\t" \
            "WAIT_DONE_%=:\n\t}" \
            :: "r"(_mbar), "r"(_parity) : "memory"); \
    } \
} while(0)

// bulk async copy GMEM -> SMEM with mbarrier complete_tx
#define BULK_G2S(dst_smem, src_gmem, nbytes, mbar) \
    asm volatile( \
        "cp.async.bulk.shared::cluster.global.mbarrier::complete_tx::bytes " \
        "[%0], [%1], %2, [%3];" \
        :: "r"((uint32_t)(dst_smem)), "l"(src_gmem), "r"((uint32_t)(nbytes)), \
           "r"((uint32_t)(mbar)) : "memory")

#define TCGEN05_LD_32X32B_X32(r, tmem_addr) \
    asm volatile( \
        "tcgen05.ld.sync.aligned.32x32b.x32.b32 " \
        "{%0, %1, %2, %3, %4, %5, %6, %7, " \
        " %8, %9, %10, %11, %12, %13, %14, %15, " \
        " %16, %17, %18, %19, %20, %21, %22, %23, " \
        " %24, %25, %26, %27, %28, %29, %30, %31}, [%32];" \
        : "=r"((r)[0]),  "=r"((r)[1]),  "=r"((r)[2]),  "=r"((r)[3]), \
          "=r"((r)[4]),  "=r"((r)[5]),  "=r"((r)[6]),  "=r"((r)[7]), \
          "=r"((r)[8]),  "=r"((r)[9]),  "=r"((r)[10]), "=r"((r)[11]), \
          "=r"((r)[12]), "=r"((r)[13]), "=r"((r)[14]), "=r"((r)[15]), \
          "=r"((r)[16]), "=r"((r)[17]), "=r"((r)[18]), "=r"((r)[19]), \
          "=r"((r)[20]), "=r"((r)[21]), "=r"((r)[22]), "=r"((r)[23]), \
          "=r"((r)[24]), "=r"((r)[25]), "=r"((r)[26]), "=r"((r)[27]), \
          "=r"((r)[28]), "=r"((r)[29]), "=r"((r)[30]), "=r"((r)[31]) \
        : "r"(tmem_addr))

// SW64 descriptor: layout=4, version=1, SBO=32 (512B atom), LBO=1 (16B)
static constexpr uint64_t SMEM_DESC_BASE_SW64 =
    (uint64_t(4)  << 61) | (uint64_t(1) << 46) |
    (uint64_t(32) << 32) | (uint64_t(1) << 16);
#define MAKE_SMEM_DESC_SW64(base_addr) \
    (SMEM_DESC_BASE_SW64 | ((uint64_t)((base_addr) >> 4) & 0x3FFF))

__device__ __forceinline__ void mma_f16_ss_cg1(
    uint32_t d_tmem, uint64_t a_desc, uint64_t b_desc,
    uint32_t idesc, uint32_t enable)
{
    asm volatile(
        "{\n\t.reg .pred p;\n\t"
        "setp.ne.u32 p, %4, 0;\n\t"
        "tcgen05.mma.cta_group::1.kind::f16 [%0], %1, %2, %3, "
        "{%5, %5, %5, %5}, p;\n\t}"
        :: "r"(d_tmem), "l"(a_desc), "l"(b_desc), "r"(idesc),
           "r"(enable), "r"(0u)
        : "memory");
}

#define GEMM_IDESC ((1u<<4)|(1u<<7)|(1u<<10)|(16u<<17)|(8u<<24))
#endif // TC_PATH

// SMEM: header 1KB + 4 stages x (Ah 16K | Al 16K | Bh 8K | Bl 8K) = 193KB
#define STAGE_BYTES 49152
#define NPIPE 4
#define GEMM_SMEM_TOTAL (1024 + NPIPE * STAGE_BYTES)

// ===========================================================================
// GEMM: C[M,N] = (Ah+Al)[M,K] @ (Bh+Bl)[N,K]^T + bias[N]
// A,B in tiled+swizzled bf16 (A: 256-row tiles, B: 128-row tiles).
// CTA computes a 256x128 tile (2 TMEM accumulators). K-chunk 32, 4-stage
// bulk-async pipeline, warp-specialized:
//   thread 0  (warp 0): MMA consumer — wait full, issue, commit. Never
//                       blocks on completion; tensor queue stays fed.
//   thread 32 (warp 1): TMA producer — 3 stages of slack between a stage's
//                       commit and the refill that depends on it, so load
//                       latency is hidden behind queued MMA work.
// 128 threads, 1 CTA/SM (193KB smem). K%128==0 (stage count mult of 4).
// ===========================================================================
__global__ __launch_bounds__(128, 1) void tc_gemm_bf16(
    const __nv_bfloat16* __restrict__ Ah, const __nv_bfloat16* __restrict__ Al,
    const __nv_bfloat16* __restrict__ Bh, const __nv_bfloat16* __restrict__ Bl,
    const float* __restrict__ bias, float* __restrict__ C,
    int M, int N, int K)
{
    extern __shared__ char smem[];
    const int tid = threadIdx.x;
    const int bm = blockIdx.y * 256;
    const int bn = blockIdx.x * 128;

#if TC_PATH
    const uint32_t smem_base = smem_u32(smem);
    const int wid  = tid >> 5;
    const int lane = tid & 31;

    // barriers: FULL[b] at 8+16b, EMPT[b] at 16+16b
#define FULLB(b) (smem_base + 8  + 16 * (b))
#define EMPTB(b) (smem_base + 16 + 16 * (b))

    if (wid == 0) {
        TCGEN05_ALLOC(smem_base, 256);
        TCGEN05_RELINQUISH_ALLOC_PERMIT();
        if (lane == 0) {
#pragma unroll
            for (int b = 0; b < NPIPE; b++) {
                MBARRIER_INIT(FULLB(b), 1);
                MBARRIER_INIT(EMPTB(b), 1);
            }
        }
    }
    __syncthreads();
    uint32_t tmem;
    asm volatile("ld.shared.b32 %0, [%1];" : "=r"(tmem) : "r"(smem_base));

    const int nstage = K >> 5;           // K-chunk 32; multiple of 4
    const int nkblk  = K >> 5;

    if (tid == 32) {
        // ---------------- producer ----------------
        const size_t arow = (size_t)(bm >> 8) * nkblk;
        const size_t brow = (size_t)(bn >> 7) * nkblk;
        int eph[NPIPE] = {0, 0, 0, 0};
        for (int s = 0; s < nstage; s++) {
            const int buf = s & (NPIPE - 1);
            const uint32_t OFF = smem_base + 1024 + buf * STAGE_BYTES;
            if (s >= NPIPE) { MBARRIER_WAIT_PARITY(EMPTB(buf), eph[buf]); eph[buf] ^= 1; }
            MBARRIER_EXPECT_TX(FULLB(buf), STAGE_BYTES);
            BULK_G2S(OFF,         (const char*)Ah + ((arow + s) << 14), 16384, FULLB(buf));
            BULK_G2S(OFF + 16384, (const char*)Al + ((arow + s) << 14), 16384, FULLB(buf));
            BULK_G2S(OFF + 32768, (const char*)Bh + ((brow + s) << 13),  8192, FULLB(buf));
            BULK_G2S(OFF + 40960, (const char*)Bl + ((brow + s) << 13),  8192, FULLB(buf));
        }
        // drain the last commit of each buffer so epilogue sees MMAs done
#pragma unroll
        for (int b = 0; b < NPIPE; b++)
            MBARRIER_WAIT_PARITY(EMPTB(b), eph[b]);
    }
    if (tid == 0) {
        // ---------------- MMA consumer ----------------
        int fph[NPIPE] = {0, 0, 0, 0};
        for (int s = 0; s < nstage; s++) {
            const int buf = s & (NPIPE - 1);
            const uint32_t OFF = smem_base + 1024 + buf * STAGE_BYTES;

            MBARRIER_WAIT_PARITY(FULLB(buf), fph[buf]); fph[buf] ^= 1;

            uint64_t a0h = MAKE_SMEM_DESC_SW64(OFF);
            uint64_t a1h = MAKE_SMEM_DESC_SW64(OFF + 8192);
            uint64_t a0l = MAKE_SMEM_DESC_SW64(OFF + 16384);
            uint64_t a1l = MAKE_SMEM_DESC_SW64(OFF + 16384 + 8192);
            uint64_t bh  = MAKE_SMEM_DESC_SW64(OFF + 32768);
            uint64_t bl  = MAKE_SMEM_DESC_SW64(OFF + 40960);
#pragma unroll
            for (int kk = 0; kk < 2; kk++) {
                uint32_t en = (s > 0 || kk > 0) ? 1u : 0u;
                mma_f16_ss_cg1(tmem,       a0h + kk*2, bh + kk*2, GEMM_IDESC, en);
                mma_f16_ss_cg1(tmem,       a0h + kk*2, bl + kk*2, GEMM_IDESC, 1u);
                mma_f16_ss_cg1(tmem,       a0l + kk*2, bh + kk*2, GEMM_IDESC, 1u);
                mma_f16_ss_cg1(tmem + 128, a1h + kk*2, bh + kk*2, GEMM_IDESC, en);
                mma_f16_ss_cg1(tmem + 128, a1h + kk*2, bl + kk*2, GEMM_IDESC, 1u);
                mma_f16_ss_cg1(tmem + 128, a1l + kk*2, bh + kk*2, GEMM_IDESC, 1u);
            }
            TCGEN05_COMMIT(EMPTB(buf));
        }
    }
    __syncthreads();   // producer's final empty-waits gate this for everyone
    TCGEN05_FENCE_AFTER();

    // Epilogue: 4 warps, two 128-row halves
#pragma unroll
    for (int half = 0; half < 2; half++) {
        const int rowo = bm + half * 128 + wid * 32 + lane;
#pragma unroll
        for (int cb = 0; cb < 128; cb += 32) {
            uint32_t d[32];
            TCGEN05_LD_32X32B_X32(d, tmem + half * 128 + cb);
            TCGEN05_WAIT_LD();
            float* crow = C + (size_t)rowo * N + bn + cb;
#pragma unroll
            for (int g = 0; g < 8; g++) {
                float4 bb = __ldg((const float4*)(bias + bn + cb + g * 4));
                float4 o;
                o.x = __uint_as_float(d[g*4+0]) + bb.x;
                o.y = __uint_as_float(d[g*4+1]) + bb.y;
                o.z = __uint_as_float(d[g*4+2]) + bb.z;
                o.w = __uint_as_float(d[g*4+3]) + bb.w;
                *(float4*)(crow + g * 4) = o;
            }
        }
    }
    __syncthreads();
    if (wid == 0) {
        TCGEN05_DEALLOC(tmem, 256);
    }
#undef FULLB
#undef EMPTB

#else
    // ---------------- FFMA fallback: 256x128 tile via tiled loads ----------
    float* As = (float*)smem;            // [8][128]
    float* Bs = (float*)(smem + 4096);

    for (int mhalf = 0; mhalf < 2; mhalf++) {
        const int bmh = bm + mhalf * 128;
        const int trow = tid >> 4;       // 0..7  (128 threads)
        const int tcol = tid & 15;
        float acc[16][8];
#pragma unroll
        for (int i = 0; i < 16; i++)
#pragma unroll
            for (int j = 0; j < 8; j++) acc[i][j] = 0.0f;

        for (int k0 = 0; k0 < K; k0 += 8) {
            for (int idx = tid; idx < 8 * 128; idx += 128) {
                int kk = idx >> 7, rr = idx & 127;
                As[kk * 128 + rr] =
                    ld_tiled(Ah, 8, bmh + rr, k0 + kk, K) +
                    ld_tiled(Al, 8, bmh + rr, k0 + kk, K);
                Bs[kk * 128 + rr] =
                    ld_tiled(Bh, 7, bn + rr, k0 + kk, K) +
                    ld_tiled(Bl, 7, bn + rr, k0 + kk, K);
            }
            __syncthreads();
#pragma unroll
            for (int kk = 0; kk < 8; kk++) {
                float a[16], b[8];
#pragma unroll
                for (int e = 0; e < 16; e++) a[e] = As[kk * 128 + trow * 16 + e];
#pragma unroll
                for (int e = 0; e < 8; e++)  b[e] = Bs[kk * 128 + tcol * 8 + e];
#pragma unroll
                for (int i = 0; i < 16; i++)
#pragma unroll
                    for (int j = 0; j < 8; j++)
                        acc[i][j] += a[i] * b[j];
            }
            __syncthreads();
        }
        const int cn = bn + tcol * 8;
#pragma unroll
        for (int i = 0; i < 16; i++) {
            const int row = bmh + trow * 16 + i;
#pragma unroll
            for (int j = 0; j < 8; j++)
                C[(size_t)row * N + cn + j] = acc[i][j] + bias[cn + j];
        }
        __syncthreads();
    }
#endif
}

// ===========================================================================
// Band attention: block = 64 queries x (h,b), 256 threads.
// Writes att in tiled+swizzled bf16 hi/lo (A-operand layout, TR=256).
// ===========================================================================
#define ATT_ROWPAD 68
#define ATT_SMEM (2 * 96 * ATT_ROWPAD * 4)

__global__ __launch_bounds__(256) void band_attn_kernel(
    const float* __restrict__ qkv, const float* __restrict__ radius,
    __nv_bfloat16* __restrict__ atth, __nv_bfloat16* __restrict__ attl)
{
    extern __shared__ float sm[];
    float* sK = sm;
    float* sV = sm + 96 * ATT_ROWPAD;

    const int tid = threadIdx.x;
    const int q0 = blockIdx.x * 64;
    const int h  = blockIdx.y;
    const int b  = blockIdx.z;

    float rr = 16.0f / (1.0f + expf(-radius[h]));
    if (rr < 1.0f) rr = 1.0f;
    const int R = (int)floorf(rr);

    const int klo = max(0, q0 - R);
    const int khi = min(SEQT - 1, q0 + 63 + R);
    const int Wt  = khi - klo + 1;   // <= 96

    const float* base = qkv + (size_t)b * SEQT * THREE_D;

    for (int i = tid; i < Wt * 16; i += 256) {
        int row = i >> 4;
        int c4  = (i & 15) * 4;
        const float* kr = base + (size_t)(klo + row) * THREE_D + DMODEL + h * HD + c4;
        *(float4*)&sK[row * ATT_ROWPAD + c4] = __ldg((const float4*)kr);
        *(float4*)&sV[row * ATT_ROWPAD + c4] = __ldg((const float4*)(kr + DMODEL));
    }

    const int pair  = tid >> 3;
    const int lane8 = tid & 7;
    const int qA = q0 + pair * 2;
    const int qB = qA + 1;

    float qFA[8], qFB[8];
    {
        const float* qa = base + (size_t)qA * THREE_D + h * HD + lane8 * 8;
        const float* qb = base + (size_t)qB * THREE_D + h * HD + lane8 * 8;
        float4 a0 = __ldg((const float4*)qa), a1 = __ldg((const float4*)(qa + 4));
        float4 b0 = __ldg((const float4*)qb), b1 = __ldg((const float4*)(qb + 4));
        qFA[0]=a0.x; qFA[1]=a0.y; qFA[2]=a0.z; qFA[3]=a0.w;
        qFA[4]=a1.x; qFA[5]=a1.y; qFA[6]=a1.z; qFA[7]=a1.w;
        qFB[0]=b0.x; qFB[1]=b0.y; qFB[2]=b0.z; qFB[3]=b0.w;
        qFB[4]=b1.x; qFB[5]=b1.y; qFB[6]=b1.z; qFB[7]=b1.w;
    }

    const int kAs = max(0, qA - R), kAe = min(SEQT - 1, qA + R);
    const int kBs = max(0, qB - R), kBe = min(SEQT - 1, qB + R);

    __syncthreads();

    float scA[34], scB[34];
#pragma unroll
    for (int m = 0; m < 34; m++) {
        const int k = kAs + m;
        float dA = 0.0f, dB = 0.0f;
        if (k <= kBe) {
            const float* kr = &sK[(k - klo) * ATT_ROWPAD + lane8 * 8];
            float4 k0 = *(const float4*)kr;
            float4 k1 = *(const float4*)(kr + 4);
            dA = qFA[0]*k0.x + qFA[1]*k0.y + qFA[2]*k0.z + qFA[3]*k0.w
               + qFA[4]*k1.x + qFA[5]*k1.y + qFA[6]*k1.z + qFA[7]*k1.w;
            dB = qFB[0]*k0.x + qFB[1]*k0.y + qFB[2]*k0.z + qFB[3]*k0.w
               + qFB[4]*k1.x + qFB[5]*k1.y + qFB[6]*k1.z + qFB[7]*k1.w;
        }
        scA[m] = dA; scB[m] = dB;
    }

#pragma unroll
    for (int m = 0; m < 34; m++) {
        scA[m] += __shfl_xor_sync(0xffffffffu, scA[m], 1);
        scA[m] += __shfl_xor_sync(0xffffffffu, scA[m], 2);
        scA[m] += __shfl_xor_sync(0xffffffffu, scA[m], 4);
        scB[m] += __shfl_xor_sync(0xffffffffu, scB[m], 1);
        scB[m] += __shfl_xor_sync(0xffffffffu, scB[m], 2);
        scB[m] += __shfl_xor_sync(0xffffffffu, scB[m], 4);
    }

    const float NEGINF = -3.402823466e38f;
    float mA = NEGINF, mB = NEGINF;
#pragma unroll
    for (int m = 0; m < 34; m++) {
        const int k = kAs + m;
        scA[m] *= 0.125f;
        scB[m] *= 0.125f;
        if (k <= kAe)             mA = fmaxf(mA, scA[m]);
        if (k >= kBs && k <= kBe) mB = fmaxf(mB, scB[m]);
    }

    float sumA = 0.0f, sumB = 0.0f;
#pragma unroll
    for (int m = 0; m < 34; m++) {
        const int k = kAs + m;
        float eA = (k <= kAe)              ? __expf(scA[m] - mA) : 0.0f;
        float eB = (k >= kBs && k <= kBe)  ? __expf(scB[m] - mB) : 0.0f;
        scA[m] = eA; scB[m] = eB;
        sumA += eA; sumB += eB;
    }
    const float invA = 1.0f / sumA;
    const float invB = 1.0f / sumB;

    float accA[8] = {0,0,0,0,0,0,0,0};
    float accB[8] = {0,0,0,0,0,0,0,0};
#pragma unroll
    for (int m = 0; m < 34; m++) {
        const int k = kAs + m;
        if (k <= kBe) {
            const float* vr = &sV[(k - klo) * ATT_ROWPAD + lane8 * 8];
            float4 v0 = *(const float4*)vr;
            float4 v1 = *(const float4*)(vr + 4);
            const float pA = scA[m] * invA;
            const float pB = scB[m] * invB;
            accA[0] += pA*v0.x; accA[1] += pA*v0.y; accA[2] += pA*v0.z; accA[3] += pA*v0.w;
            accA[4] += pA*v1.x; accA[5] += pA*v1.y; accA[6] += pA*v1.z; accA[7] += pA*v1.w;
            accB[0] += pB*v0.x; accB[1] += pB*v0.y; accB[2] += pB*v0.z; accB[3] += pB*v0.w;
            accB[4] += pB*v1.x; accB[5] += pB*v1.y; accB[6] += pB*v1.z; accB[7] += pB*v1.w;
        }
    }

    // write att in tiled+swizzled layout (TR=256, K=512 -> 16 kblks/row-tile)
    {
        uint4 hA, lA, hB, lB;
        uint32_t* ph = (uint32_t*)&hA; uint32_t* pl = (uint32_t*)&lA;
#pragma unroll
        for (int g = 0; g < 4; g++) {
            __nv_bfloat16 h0, l0, h1, l1;
            split_hilo(accA[g*2],   h0, l0);
            split_hilo(accA[g*2+1], h1, l1);
            ph[g] = pack_bf16x2(h0, h1);
            pl[g] = pack_bf16x2(l0, l1);
        }
        uint32_t* phb = (uint32_t*)&hB; uint32_t* plb = (uint32_t*)&lB;
#pragma unroll
        for (int g = 0; g < 4; g++) {
            __nv_bfloat16 h0, l0, h1, l1;
            split_hilo(accB[g*2],   h0, l0);
            split_hilo(accB[g*2+1], h1, l1);
            phb[g] = pack_bf16x2(h0, h1);
            plb[g] = pack_bf16x2(l0, l1);
        }
        const int col8 = h * 8 + lane8;          // 8-elem col group
        const int kblk = col8 >> 2, cc = col8 & 3;
        const int rowA = b * SEQT + qA;
        const int rowB = rowA + 1;
        size_t tA = ((size_t)((rowA >> 8) * 16 + kblk)) << 14;
        size_t tB = ((size_t)((rowB >> 8) * 16 + kblk)) << 14;
        uint32_t boA = sw64((uint32_t)((rowA & 255) * 64 + cc * 16));
        uint32_t boB = sw64((uint32_t)((rowB & 255) * 64 + cc * 16));
        *(uint4*)((char*)atth + tA + boA) = hA;
        *(uint4*)((char*)attl + tA + boA) = lA;
        *(uint4*)((char*)atth + tB + boB) = hB;
        *(uint4*)((char*)attl + tB + boB) = lB;
    }
}

// ---------------------------------------------------------------------------
extern "C" void kernel_launch(void* const* d_in, const int* in_sizes, int n_in,
                              void* d_out, int out_size)
{
    const float* x      = (const float*)d_in[0];
    const float* radius = (const float*)d_in[1];
    const float* w_in   = (const float*)d_in[2];
    const float* b_in   = (const float*)d_in[3];
    const float* w_out  = (const float*)d_in[4];
    const float* b_out  = (const float*)d_in[5];
    float* out = (float*)d_out;

    float *qkv;
    __nv_bfloat16 *xh, *xl, *wih, *wil, *woh, *wol, *atth, *attl;
    cudaGetSymbolAddress((void**)&qkv,  g_qkv);
    cudaGetSymbolAddress((void**)&xh,   g_xh);
    cudaGetSymbolAddress((void**)&xl,   g_xl);
    cudaGetSymbolAddress((void**)&wih,  g_wih);
    cudaGetSymbolAddress((void**)&wil,  g_wil);
    cudaGetSymbolAddress((void**)&woh,  g_woh);
    cudaGetSymbolAddress((void**)&wol,  g_wol);
    cudaGetSymbolAddress((void**)&atth, g_atth);
    cudaGetSymbolAddress((void**)&attl, g_attl);

    cudaFuncSetAttribute(tc_gemm_bf16,
                         cudaFuncAttributeMaxDynamicSharedMemorySize,
                         GEMM_SMEM_TOTAL);
    cudaFuncSetAttribute(band_attn_kernel,
                         cudaFuncAttributeMaxDynamicSharedMemorySize,
                         ATT_SMEM);

    // 0) fp32 -> tiled+swizzled bf16 hi/lo
    {
        int n8;
        n8 = (MROWS * DMODEL) / 8;     // x: A operand, TR=256
        cvt_tiled_kernel<8><<<(n8 + 255) / 256, 256>>>(x, xh, xl, MROWS, DMODEL);
        n8 = (THREE_D * DMODEL) / 8;   // w_in: B operand, TR=128
        cvt_tiled_kernel<7><<<(n8 + 255) / 256, 256>>>(w_in, wih, wil, THREE_D, DMODEL);
        n8 = (DMODEL * DMODEL) / 8;    // w_out: B operand, TR=128
        cvt_tiled_kernel<7><<<(n8 + 255) / 256, 256>>>(w_out, woh, wol, DMODEL, DMODEL);
    }

    // 1) QKV projection: [8192,512] x [1536,512]^T -> [8192,1536] fp32
    {
        dim3 grid(THREE_D / 128, MROWS / 256);
        tc_gemm_bf16<<<grid, 128, GEMM_SMEM_TOTAL>>>(
            xh, xl, wih, wil, b_in, qkv, MROWS, THREE_D, DMODEL);
    }

    // 2) Band attention -> att (tiled bf16 hi/lo)
    {
        dim3 grid(SEQT / 64, NHEAD, BATCH);
        band_attn_kernel<<<grid, 256, ATT_SMEM>>>(qkv, radius, atth, attl);
    }

    // 3) Output projection: [8192,512] x [512,512]^T -> out fp32
    {
        dim3 grid(DMODEL / 128, MROWS / 256);
        tc_gemm_bf16<<<grid, 128, GEMM_SMEM_TOTAL>>>(
            atth, attl, woh, wol, b_out, out, MROWS, DMODEL, DMODEL);
    }
}

// round 10
// speedup vs baseline: 1.0564x; 1.0564x over previous
#include <cuda_runtime.h>
#include <cuda_bf16.h>
#include <cstdint>

// Problem constants
#define BATCH 4
#define SEQT  2048
#define DMODEL 512
#define NHEAD 8
#define HD    64
#define THREE_D (3 * DMODEL)
#define MROWS (BATCH * SEQT)        // 8192

// Arch-feature dispatch: tcgen05/bulk-async only on *a targets.
#if !defined(__CUDA_ARCH__)
#  define TC_PATH 1
#elif defined(__CUDA_ARCH_HAS_FEATURE__) && \
      (__CUDA_ARCH_HAS_FEATURE__(SM103_ALL) || __CUDA_ARCH_HAS_FEATURE__(SM100_ALL))
#  define TC_PATH 1
#else
#  define TC_PATH 0
#endif

// ---------------------------------------------------------------------------
// Tiled+swizzled bf16 operand layout (SW64), TR=128 rows per tile:
//   tile (rblk, kblk) is contiguous 128*64 bytes (8KB) at
//     ((rblk * (K/32) + kblk) << 13)
//   within tile: row r, col c (bf16): bo = r*64 + c*2, swizzled bo^=((bo>>3)&0x30)
// ---------------------------------------------------------------------------

// Scratch (no cudaMalloc allowed)
__device__ float g_qkv[(size_t)MROWS * THREE_D];   // 48 MB fp32
__device__ alignas(128) __nv_bfloat16 g_xh[(size_t)MROWS * DMODEL];
__device__ alignas(128) __nv_bfloat16 g_xl[(size_t)MROWS * DMODEL];
__device__ alignas(128) __nv_bfloat16 g_wih[(size_t)THREE_D * DMODEL];
__device__ alignas(128) __nv_bfloat16 g_wil[(size_t)THREE_D * DMODEL];
__device__ alignas(128) __nv_bfloat16 g_woh[(size_t)DMODEL * DMODEL];
__device__ alignas(128) __nv_bfloat16 g_wol[(size_t)DMODEL * DMODEL];
__device__ alignas(128) __nv_bfloat16 g_atth[(size_t)MROWS * DMODEL];
__device__ alignas(128) __nv_bfloat16 g_attl[(size_t)MROWS * DMODEL];

// ===========================================================================
// Common helpers
// ===========================================================================
__device__ __forceinline__ uint32_t pack_bf16x2(__nv_bfloat16 a, __nv_bfloat16 b) {
    return (uint32_t)__bfloat16_as_ushort(a) |
           ((uint32_t)__bfloat16_as_ushort(b) << 16);
}

__device__ __forceinline__ void split_hilo(float v, __nv_bfloat16& h, __nv_bfloat16& l) {
    h = __float2bfloat16(v);
    l = __float2bfloat16(v - __bfloat162float(h));
}

__device__ __forceinline__ uint32_t sw64(uint32_t bo) {
    return bo ^ ((bo >> 3) & 0x30);
}

// tiled element load (fallback path only), TR=128
__device__ __forceinline__ float ld_tiled(
    const __nv_bfloat16* base, int row, int col, int Kdim)
{
    int kblk = col >> 5, cin = col & 31;
    int rblk = row >> 7, rin = row & 127;
    size_t tile = ((size_t)(rblk * (Kdim >> 5) + kblk)) << 13;
    uint32_t bo = sw64((uint32_t)(rin * 64 + cin * 2));
    return __bfloat162float(*(const __nv_bfloat16*)((const char*)base + tile + bo));
}

// ===========================================================================
// fp32 row-major -> tiled+swizzled bf16 hi/lo (TR=128). 8 elems/thread.
// ===========================================================================
__global__ __launch_bounds__(256) void cvt_tiled_kernel(
    const float* __restrict__ src,
    __nv_bfloat16* __restrict__ dh, __nv_bfloat16* __restrict__ dl,
    int R, int Kdim)
{
    int i = blockIdx.x * blockDim.x + threadIdx.x;   // 8-elem granule
    int n8 = (R * Kdim) >> 3;
    if (i >= n8) return;
    const int K8 = Kdim >> 3;
    int row = i / K8;
    int c8  = i - row * K8;

    float4 v0 = __ldg((const float4*)src + i * 2);
    float4 v1 = __ldg((const float4*)src + i * 2 + 1);

    __nv_bfloat16 h0,l0,h1,l1,h2,l2,h3,l3,h4,l4,h5,l5,h6,l6,h7,l7;
    split_hilo(v0.x,h0,l0); split_hilo(v0.y,h1,l1);
    split_hilo(v0.z,h2,l2); split_hilo(v0.w,h3,l3);
    split_hilo(v1.x,h4,l4); split_hilo(v1.y,h5,l5);
    split_hilo(v1.z,h6,l6); split_hilo(v1.w,h7,l7);
    uint4 hi, lo;
    hi.x = pack_bf16x2(h0,h1); hi.y = pack_bf16x2(h2,h3);
    hi.z = pack_bf16x2(h4,h5); hi.w = pack_bf16x2(h6,h7);
    lo.x = pack_bf16x2(l0,l1); lo.y = pack_bf16x2(l2,l3);
    lo.z = pack_bf16x2(l4,l5); lo.w = pack_bf16x2(l6,l7);

    int kblk = c8 >> 2, cc = c8 & 3;
    int rblk = row >> 7, rin = row & 127;
    size_t tile = ((size_t)(rblk * (Kdim >> 5) + kblk)) << 13;
    uint32_t bo = sw64((uint32_t)(rin * 64 + cc * 16));
    *(uint4*)((char*)dh + tile + bo) = hi;
    *(uint4*)((char*)dl + tile + bo) = lo;
}

// ===========================================================================
// tcgen05 + bulk-async PTX helpers (feature-gated)
// ===========================================================================
#if TC_PATH
__device__ __forceinline__ uint32_t smem_u32(const void* p) {
    uint32_t a;
    asm("{ .reg .u64 t; cvta.to.shared.u64 t, %1; cvt.u32.u64 %0, t; }"
        : "=r"(a) : "l"(p));
    return a;
}

#define TCGEN05_ALLOC(smem_result_addr, nCols) \
    asm volatile( \
        "tcgen05.alloc.cta_group::1.sync.aligned.shared::cta.b32 [%0], %1;" \
        :: "r"((uint32_t)(smem_result_addr)), "r"((uint32_t)(nCols)) : "memory")

#define TCGEN05_DEALLOC(tmem_addr, nCols) \
    asm volatile( \
        "tcgen05.dealloc.cta_group::1.sync.aligned.b32 %0, %1;" \
        :: "r"(tmem_addr), "r"((uint32_t)(nCols)))

#define TCGEN05_RELINQUISH_ALLOC_PERMIT() \
    asm volatile("tcgen05.relinquish_alloc_permit.cta_group::1.sync.aligned;")

#define TCGEN05_COMMIT(mbar_smem_addr) \
    asm volatile( \
        "tcgen05.commit.cta_group::1.mbarrier::arrive::one.shared::cluster.b64 [%0];" \
        :: "r"((uint32_t)(mbar_smem_addr)) : "memory")

#define TCGEN05_FENCE_AFTER() \
    asm volatile("tcgen05.fence::after_thread_sync;" ::: "memory")

#define TCGEN05_WAIT_LD() \
    asm volatile("tcgen05.wait::ld.sync.aligned;" ::: "memory")

#define MBARRIER_INIT(mbar_smem_addr, count) \
    asm volatile( \
        "mbarrier.init.shared.b64 [%0], %1;" \
        :: "r"((uint32_t)(mbar_smem_addr)), "r"((uint32_t)(count)) : "memory")

#define MBARRIER_EXPECT_TX(mbar_smem_addr, tx_bytes) \
    asm volatile( \
        "mbarrier.arrive.expect_tx.shared.b64 _, [%0], %1;" \
        :: "r"((uint32_t)(mbar_smem_addr)), "r"((uint32_t)(tx_bytes)) : "memory")

#define MBARRIER_WAIT_PARITY(mbar_smem_addr, phase_parity) do { \
    uint32_t _mbar = (uint32_t)(mbar_smem_addr); \
    uint32_t _parity = (uint32_t)(phase_parity); \
    uint32_t _done; \
    asm volatile( \
        "{\n\t.reg .pred p;\n\t" \
        "mbarrier.try_wait.parity.acquire.cta.shared::cta.b64 p, [%1], %2;\n\t" \
        "selp.b32 %0, 1, 0, p;\n\t}" \
        : "=r"(_done) : "r"(_mbar), "r"(_parity) : "memory"); \
    if (!_done) { \
        asm volatile( \
            "{\n\t.reg .pred P1;\n\t" \
            "WAIT_LOOP_%=:\n\t" \
            "mbarrier.try_wait.parity.acquire.cta.shared::cta.b64 P1, [%0], %1, 0x989680;\n\t" \
            "@P1 bra.uni WAIT_DONE_%=;\n\t" \
            "bra.uni WAIT_LOOP_%=;\n\t" \
            "WAIT_DONE_%=:\n\t}" \
            :: "r"(_mbar), "r"(_parity) : "memory"); \
    } \
} while(0)

// bulk async copy GMEM -> SMEM with mbarrier complete_tx
#define BULK_G2S(dst_smem, src_gmem, nbytes, mbar) \
    asm volatile( \
        "cp.async.bulk.shared::cluster.global.mbarrier::complete_tx::bytes " \
        "[%0], [%1], %2, [%3];" \
        :: "r"((uint32_t)(dst_smem)), "l"(src_gmem), "r"((uint32_t)(nbytes)), \
           "r"((uint32_t)(mbar)) : "memory")

#define TCGEN05_LD_32X32B_X32(r, tmem_addr) \
    asm volatile( \
        "tcgen05.ld.sync.aligned.32x32b.x32.b32 " \
        "{%0, %1, %2, %3, %4, %5, %6, %7, " \
        " %8, %9, %10, %11, %12, %13, %14, %15, " \
        " %16, %17, %18, %19, %20, %21, %22, %23, " \
        " %24, %25, %26, %27, %28, %29, %30, %31}, [%32];" \
        : "=r"((r)[0]),  "=r"((r)[1]),  "=r"((r)[2]),  "=r"((r)[3]), \
          "=r"((r)[4]),  "=r"((r)[5]),  "=r"((r)[6]),  "=r"((r)[7]), \
          "=r"((r)[8]),  "=r"((r)[9]),  "=r"((r)[10]), "=r"((r)[11]), \
          "=r"((r)[12]), "=r"((r)[13]), "=r"((r)[14]), "=r"((r)[15]), \
          "=r"((r)[16]), "=r"((r)[17]), "=r"((r)[18]), "=r"((r)[19]), \
          "=r"((r)[20]), "=r"((r)[21]), "=r"((r)[22]), "=r"((r)[23]), \
          "=r"((r)[24]), "=r"((r)[25]), "=r"((r)[26]), "=r"((r)[27]), \
          "=r"((r)[28]), "=r"((r)[29]), "=r"((r)[30]), "=r"((r)[31]) \
        : "r"(tmem_addr))

// SW64 descriptor: layout=4, version=1, SBO=32 (512B atom), LBO=1 (16B)
static constexpr uint64_t SMEM_DESC_BASE_SW64 =
    (uint64_t(4)  << 61) | (uint64_t(1) << 46) |
    (uint64_t(32) << 32) | (uint64_t(1) << 16);
#define MAKE_SMEM_DESC_SW64(base_addr) \
    (SMEM_DESC_BASE_SW64 | ((uint64_t)((base_addr) >> 4) & 0x3FFF))

__device__ __forceinline__ void mma_f16_ss_cg1(
    uint32_t d_tmem, uint64_t a_desc, uint64_t b_desc,
    uint32_t idesc, uint32_t enable)
{
    asm volatile(
        "{\n\t.reg .pred p;\n\t"
        "setp.ne.u32 p, %4, 0;\n\t"
        "tcgen05.mma.cta_group::1.kind::f16 [%0], %1, %2, %3, "
        "{%5, %5, %5, %5}, p;\n\t}"
        :: "r"(d_tmem), "l"(a_desc), "l"(b_desc), "r"(idesc),
           "r"(enable), "r"(0u)
        : "memory");
}

#define GEMM_IDESC ((1u<<4)|(1u<<7)|(1u<<10)|(16u<<17)|(8u<<24))  // M128 N128 bf16 f32acc
#endif // TC_PATH

// SMEM: header 1KB + 3 stages x (Ah 8K | Al 8K | Bh 8K | Bl 8K) = 97KB
#define STAGE_BYTES 32768
#define NPIPE 3
#define GEMM_SMEM_TOTAL (1024 + NPIPE * STAGE_BYTES)

// ===========================================================================
// GEMM: C[M,N] = (Ah+Al)[M,K] @ (Bh+Bl)[N,K]^T + bias[N]
// A,B in tiled+swizzled bf16 (both TR=128 tiles). CTA computes 128x128
// (1 TMEM accumulator, 128 cols). K-chunk 32, 3-stage bulk-async pipeline,
// warp-specialized:
//   thread 0  (warp 0): MMA consumer — wait full, issue 6 MMAs, commit.
//   thread 32 (warp 1): TMA producer — 2 stages of slack between a stage's
//                       commit and its refill, hides TMA round-trip.
// 128 threads, 2 CTAs/SM (97KB smem each, 2x128 TMEM cols). K%96 not needed;
// K%32==0 suffices.
// ===========================================================================
__global__ __launch_bounds__(128, 2) void tc_gemm_bf16(
    const __nv_bfloat16* __restrict__ Ah, const __nv_bfloat16* __restrict__ Al,
    const __nv_bfloat16* __restrict__ Bh, const __nv_bfloat16* __restrict__ Bl,
    const float* __restrict__ bias, float* __restrict__ C,
    int M, int N, int K)
{
    extern __shared__ char smem[];
    const int tid = threadIdx.x;
    const int bm = blockIdx.y * 128;
    const int bn = blockIdx.x * 128;

#if TC_PATH
    const uint32_t smem_base = smem_u32(smem);
    const int wid  = tid >> 5;
    const int lane = tid & 31;

    // barriers: FULL[b] at 8+16b, EMPT[b] at 16+16b  (b = 0..2)
#define FULLB(b) (smem_base + 8  + 16 * (b))
#define EMPTB(b) (smem_base + 16 + 16 * (b))

    if (wid == 0) {
        TCGEN05_ALLOC(smem_base, 128);
        TCGEN05_RELINQUISH_ALLOC_PERMIT();
        if (lane == 0) {
#pragma unroll
            for (int b = 0; b < NPIPE; b++) {
                MBARRIER_INIT(FULLB(b), 1);
                MBARRIER_INIT(EMPTB(b), 1);
            }
        }
    }
    __syncthreads();
    uint32_t tmem;
    asm volatile("ld.shared.b32 %0, [%1];" : "=r"(tmem) : "r"(smem_base));

    const int nstage = K >> 5;           // K-chunk 32
    const int nkblk  = K >> 5;

    if (tid == 32) {
        // ---------------- producer ----------------
        const size_t arow = (size_t)(bm >> 7) * nkblk;
        const size_t brow = (size_t)(bn >> 7) * nkblk;
        int eph[NPIPE] = {0, 0, 0};
        int buf = 0;
        for (int s = 0; s < nstage; s++) {
            const uint32_t OFF = smem_base + 1024 + buf * STAGE_BYTES;
            if (s >= NPIPE) { MBARRIER_WAIT_PARITY(EMPTB(buf), eph[buf]); eph[buf] ^= 1; }
            MBARRIER_EXPECT_TX(FULLB(buf), STAGE_BYTES);
            BULK_G2S(OFF,         (const char*)Ah + ((arow + s) << 13), 8192, FULLB(buf));
            BULK_G2S(OFF +  8192, (const char*)Al + ((arow + s) << 13), 8192, FULLB(buf));
            BULK_G2S(OFF + 16384, (const char*)Bh + ((brow + s) << 13), 8192, FULLB(buf));
            BULK_G2S(OFF + 24576, (const char*)Bl + ((brow + s) << 13), 8192, FULLB(buf));
            if (++buf == NPIPE) buf = 0;
        }
        // drain the last commit of each buffer so epilogue sees MMAs done
#pragma unroll
        for (int b = 0; b < NPIPE; b++)
            MBARRIER_WAIT_PARITY(EMPTB(b), eph[b]);
    }
    if (tid == 0) {
        // ---------------- MMA consumer ----------------
        int fph[NPIPE] = {0, 0, 0};
        int buf = 0;
        for (int s = 0; s < nstage; s++) {
            const uint32_t OFF = smem_base + 1024 + buf * STAGE_BYTES;

            MBARRIER_WAIT_PARITY(FULLB(buf), fph[buf]); fph[buf] ^= 1;

            uint64_t ah = MAKE_SMEM_DESC_SW64(OFF);
            uint64_t al = MAKE_SMEM_DESC_SW64(OFF + 8192);
            uint64_t bh = MAKE_SMEM_DESC_SW64(OFF + 16384);
            uint64_t bl = MAKE_SMEM_DESC_SW64(OFF + 24576);
#pragma unroll
            for (int kk = 0; kk < 2; kk++) {
                uint32_t en = (s > 0 || kk > 0) ? 1u : 0u;
                mma_f16_ss_cg1(tmem, ah + kk*2, bh + kk*2, GEMM_IDESC, en);
                mma_f16_ss_cg1(tmem, ah + kk*2, bl + kk*2, GEMM_IDESC, 1u);
                mma_f16_ss_cg1(tmem, al + kk*2, bh + kk*2, GEMM_IDESC, 1u);
            }
            TCGEN05_COMMIT(EMPTB(buf));
            if (++buf == NPIPE) buf = 0;
        }
    }
    __syncthreads();   // producer's final empty-waits gate this for everyone
    TCGEN05_FENCE_AFTER();

    // Epilogue: 4 warps read the 128x128 fp32 accumulator
    {
        const int rowo = bm + wid * 32 + lane;
#pragma unroll
        for (int cb = 0; cb < 128; cb += 32) {
            uint32_t d[32];
            TCGEN05_LD_32X32B_X32(d, tmem + cb);
            TCGEN05_WAIT_LD();
            float* crow = C + (size_t)rowo * N + bn + cb;
#pragma unroll
            for (int g = 0; g < 8; g++) {
                float4 bb = __ldg((const float4*)(bias + bn + cb + g * 4));
                float4 o;
                o.x = __uint_as_float(d[g*4+0]) + bb.x;
                o.y = __uint_as_float(d[g*4+1]) + bb.y;
                o.z = __uint_as_float(d[g*4+2]) + bb.z;
                o.w = __uint_as_float(d[g*4+3]) + bb.w;
                *(float4*)(crow + g * 4) = o;
            }
        }
    }
    __syncthreads();
    if (wid == 0) {
        TCGEN05_DEALLOC(tmem, 128);
    }
#undef FULLB
#undef EMPTB

#else
    // ---------------- FFMA fallback: 128x128 tile via tiled loads ----------
    float* As = (float*)smem;            // [8][128]
    float* Bs = (float*)(smem + 4096);

    const int trow = tid >> 4;           // 0..7
    const int tcol = tid & 15;
    float acc[16][8];
#pragma unroll
    for (int i = 0; i < 16; i++)
#pragma unroll
        for (int j = 0; j < 8; j++) acc[i][j] = 0.0f;

    for (int k0 = 0; k0 < K; k0 += 8) {
        for (int idx = tid; idx < 8 * 128; idx += 128) {
            int kk = idx >> 7, rr = idx & 127;
            As[kk * 128 + rr] =
                ld_tiled(Ah, bm + rr, k0 + kk, K) +
                ld_tiled(Al, bm + rr, k0 + kk, K);
            Bs[kk * 128 + rr] =
                ld_tiled(Bh, bn + rr, k0 + kk, K) +
                ld_tiled(Bl, bn + rr, k0 + kk, K);
        }
        __syncthreads();
#pragma unroll
        for (int kk = 0; kk < 8; kk++) {
            float a[16], b[8];
#pragma unroll
            for (int e = 0; e < 16; e++) a[e] = As[kk * 128 + trow * 16 + e];
#pragma unroll
            for (int e = 0; e < 8; e++)  b[e] = Bs[kk * 128 + tcol * 8 + e];
#pragma unroll
            for (int i = 0; i < 16; i++)
#pragma unroll
                for (int j = 0; j < 8; j++)
                    acc[i][j] += a[i] * b[j];
        }
        __syncthreads();
    }
    const int cn = bn + tcol * 8;
#pragma unroll
    for (int i = 0; i < 16; i++) {
        const int row = bm + trow * 16 + i;
#pragma unroll
        for (int j = 0; j < 8; j++)
            C[(size_t)row * N + cn + j] = acc[i][j] + bias[cn + j];
    }
#endif
}

// ===========================================================================
// Band attention: block = 64 queries x (h,b), 256 threads.
// Writes att in tiled+swizzled bf16 hi/lo (TR=128).
// ===========================================================================
#define ATT_ROWPAD 68
#define ATT_SMEM (2 * 96 * ATT_ROWPAD * 4)

__global__ __launch_bounds__(256) void band_attn_kernel(
    const float* __restrict__ qkv, const float* __restrict__ radius,
    __nv_bfloat16* __restrict__ atth, __nv_bfloat16* __restrict__ attl)
{
    extern __shared__ float sm[];
    float* sK = sm;
    float* sV = sm + 96 * ATT_ROWPAD;

    const int tid = threadIdx.x;
    const int q0 = blockIdx.x * 64;
    const int h  = blockIdx.y;
    const int b  = blockIdx.z;

    float rr = 16.0f / (1.0f + expf(-radius[h]));
    if (rr < 1.0f) rr = 1.0f;
    const int R = (int)floorf(rr);

    const int klo = max(0, q0 - R);
    const int khi = min(SEQT - 1, q0 + 63 + R);
    const int Wt  = khi - klo + 1;   // <= 96

    const float* base = qkv + (size_t)b * SEQT * THREE_D;

    for (int i = tid; i < Wt * 16; i += 256) {
        int row = i >> 4;
        int c4  = (i & 15) * 4;
        const float* kr = base + (size_t)(klo + row) * THREE_D + DMODEL + h * HD + c4;
        *(float4*)&sK[row * ATT_ROWPAD + c4] = __ldg((const float4*)kr);
        *(float4*)&sV[row * ATT_ROWPAD + c4] = __ldg((const float4*)(kr + DMODEL));
    }

    const int pair  = tid >> 3;
    const int lane8 = tid & 7;
    const int qA = q0 + pair * 2;
    const int qB = qA + 1;

    float qFA[8], qFB[8];
    {
        const float* qa = base + (size_t)qA * THREE_D + h * HD + lane8 * 8;
        const float* qb = base + (size_t)qB * THREE_D + h * HD + lane8 * 8;
        float4 a0 = __ldg((const float4*)qa), a1 = __ldg((const float4*)(qa + 4));
        float4 b0 = __ldg((const float4*)qb), b1 = __ldg((const float4*)(qb + 4));
        qFA[0]=a0.x; qFA[1]=a0.y; qFA[2]=a0.z; qFA[3]=a0.w;
        qFA[4]=a1.x; qFA[5]=a1.y; qFA[6]=a1.z; qFA[7]=a1.w;
        qFB[0]=b0.x; qFB[1]=b0.y; qFB[2]=b0.z; qFB[3]=b0.w;
        qFB[4]=b1.x; qFB[5]=b1.y; qFB[6]=b1.z; qFB[7]=b1.w;
    }

    const int kAs = max(0, qA - R), kAe = min(SEQT - 1, qA + R);
    const int kBs = max(0, qB - R), kBe = min(SEQT - 1, qB + R);

    __syncthreads();

    float scA[34], scB[34];
#pragma unroll
    for (int m = 0; m < 34; m++) {
        const int k = kAs + m;
        float dA = 0.0f, dB = 0.0f;
        if (k <= kBe) {
            const float* kr = &sK[(k - klo) * ATT_ROWPAD + lane8 * 8];
            float4 k0 = *(const float4*)kr;
            float4 k1 = *(const float4*)(kr + 4);
            dA = qFA[0]*k0.x + qFA[1]*k0.y + qFA[2]*k0.z + qFA[3]*k0.w
               + qFA[4]*k1.x + qFA[5]*k1.y + qFA[6]*k1.z + qFA[7]*k1.w;
            dB = qFB[0]*k0.x + qFB[1]*k0.y + qFB[2]*k0.z + qFB[3]*k0.w
               + qFB[4]*k1.x + qFB[5]*k1.y + qFB[6]*k1.z + qFB[7]*k1.w;
        }
        scA[m] = dA; scB[m] = dB;
    }

#pragma unroll
    for (int m = 0; m < 34; m++) {
        scA[m] += __shfl_xor_sync(0xffffffffu, scA[m], 1);
        scA[m] += __shfl_xor_sync(0xffffffffu, scA[m], 2);
        scA[m] += __shfl_xor_sync(0xffffffffu, scA[m], 4);
        scB[m] += __shfl_xor_sync(0xffffffffu, scB[m], 1);
        scB[m] += __shfl_xor_sync(0xffffffffu, scB[m], 2);
        scB[m] += __shfl_xor_sync(0xffffffffu, scB[m], 4);
    }

    const float NEGINF = -3.402823466e38f;
    float mA = NEGINF, mB = NEGINF;
#pragma unroll
    for (int m = 0; m < 34; m++) {
        const int k = kAs + m;
        scA[m] *= 0.125f;
        scB[m] *= 0.125f;
        if (k <= kAe)             mA = fmaxf(mA, scA[m]);
        if (k >= kBs && k <= kBe) mB = fmaxf(mB, scB[m]);
    }

    float sumA = 0.0f, sumB = 0.0f;
#pragma unroll
    for (int m = 0; m < 34; m++) {
        const int k = kAs + m;
        float eA = (k <= kAe)              ? __expf(scA[m] - mA) : 0.0f;
        float eB = (k >= kBs && k <= kBe)  ? __expf(scB[m] - mB) : 0.0f;
        scA[m] = eA; scB[m] = eB;
        sumA += eA; sumB += eB;
    }
    const float invA = 1.0f / sumA;
    const float invB = 1.0f / sumB;

    float accA[8] = {0,0,0,0,0,0,0,0};
    float accB[8] = {0,0,0,0,0,0,0,0};
#pragma unroll
    for (int m = 0; m < 34; m++) {
        const int k = kAs + m;
        if (k <= kBe) {
            const float* vr = &sV[(k - klo) * ATT_ROWPAD + lane8 * 8];
            float4 v0 = *(const float4*)vr;
            float4 v1 = *(const float4*)(vr + 4);
            const float pA = scA[m] * invA;
            const float pB = scB[m] * invB;
            accA[0] += pA*v0.x; accA[1] += pA*v0.y; accA[2] += pA*v0.z; accA[3] += pA*v0.w;
            accA[4] += pA*v1.x; accA[5] += pA*v1.y; accA[6] += pA*v1.z; accA[7] += pA*v1.w;
            accB[0] += pB*v0.x; accB[1] += pB*v0.y; accB[2] += pB*v0.z; accB[3] += pB*v0.w;
            accB[4] += pB*v1.x; accB[5] += pB*v1.y; accB[6] += pB*v1.z; accB[7] += pB*v1.w;
        }
    }

    // write att in tiled+swizzled layout (TR=128, K=512 -> 16 kblks/row-tile)
    {
        uint4 hA, lA, hB, lB;
        uint32_t* ph = (uint32_t*)&hA; uint32_t* pl = (uint32_t*)&lA;
#pragma unroll
        for (int g = 0; g < 4; g++) {
            __nv_bfloat16 h0, l0, h1, l1;
            split_hilo(accA[g*2],   h0, l0);
            split_hilo(accA[g*2+1], h1, l1);
            ph[g] = pack_bf16x2(h0, h1);
            pl[g] = pack_bf16x2(l0, l1);
        }
        uint32_t* phb = (uint32_t*)&hB; uint32_t* plb = (uint32_t*)&lB;
#pragma unroll
        for (int g = 0; g < 4; g++) {
            __nv_bfloat16 h0, l0, h1, l1;
            split_hilo(accB[g*2],   h0, l0);
            split_hilo(accB[g*2+1], h1, l1);
            phb[g] = pack_bf16x2(h0, h1);
            plb[g] = pack_bf16x2(l0, l1);
        }
        const int col8 = h * 8 + lane8;          // 8-elem col group
        const int kblk = col8 >> 2, cc = col8 & 3;
        const int rowA = b * SEQT + qA;
        const int rowB = rowA + 1;
        size_t tA = ((size_t)((rowA >> 7) * 16 + kblk)) << 13;
        size_t tB = ((size_t)((rowB >> 7) * 16 + kblk)) << 13;
        uint32_t boA = sw64((uint32_t)((rowA & 127) * 64 + cc * 16));
        uint32_t boB = sw64((uint32_t)((rowB & 127) * 64 + cc * 16));
        *(uint4*)((char*)atth + tA + boA) = hA;
        *(uint4*)((char*)attl + tA + boA) = lA;
        *(uint4*)((char*)atth + tB + boB) = hB;
        *(uint4*)((char*)attl + tB + boB) = lB;
    }
}

// ---------------------------------------------------------------------------
extern "C" void kernel_launch(void* const* d_in, const int* in_sizes, int n_in,
                              void* d_out, int out_size)
{
    const float* x      = (const float*)d_in[0];
    const float* radius = (const float*)d_in[1];
    const float* w_in   = (const float*)d_in[2];
    const float* b_in   = (const float*)d_in[3];
    const float* w_out  = (const float*)d_in[4];
    const float* b_out  = (const float*)d_in[5];
    float* out = (float*)d_out;

    float *qkv;
    __nv_bfloat16 *xh, *xl, *wih, *wil, *woh, *wol, *atth, *attl;
    cudaGetSymbolAddress((void**)&qkv,  g_qkv);
    cudaGetSymbolAddress((void**)&xh,   g_xh);
    cudaGetSymbolAddress((void**)&xl,   g_xl);
    cudaGetSymbolAddress((void**)&wih,  g_wih);
    cudaGetSymbolAddress((void**)&wil,  g_wil);
    cudaGetSymbolAddress((void**)&woh,  g_woh);
    cudaGetSymbolAddress((void**)&wol,  g_wol);
    cudaGetSymbolAddress((void**)&atth, g_atth);
    cudaGetSymbolAddress((void**)&attl, g_attl);

    cudaFuncSetAttribute(tc_gemm_bf16,
                         cudaFuncAttributeMaxDynamicSharedMemorySize,
                         GEMM_SMEM_TOTAL);
    cudaFuncSetAttribute(band_attn_kernel,
                         cudaFuncAttributeMaxDynamicSharedMemorySize,
                         ATT_SMEM);

    // 0) fp32 -> tiled+swizzled bf16 hi/lo (all TR=128)
    {
        int n8;
        n8 = (MROWS * DMODEL) / 8;
        cvt_tiled_kernel<<<(n8 + 255) / 256, 256>>>(x, xh, xl, MROWS, DMODEL);
        n8 = (THREE_D * DMODEL) / 8;
        cvt_tiled_kernel<<<(n8 + 255) / 256, 256>>>(w_in, wih, wil, THREE_D, DMODEL);
        n8 = (DMODEL * DMODEL) / 8;
        cvt_tiled_kernel<<<(n8 + 255) / 256, 256>>>(w_out, woh, wol, DMODEL, DMODEL);
    }

    // 1) QKV projection: [8192,512] x [1536,512]^T -> [8192,1536] fp32
    {
        dim3 grid(THREE_D / 128, MROWS / 128);
        tc_gemm_bf16<<<grid, 128, GEMM_SMEM_TOTAL>>>(
            xh, xl, wih, wil, b_in, qkv, MROWS, THREE_D, DMODEL);
    }

    // 2) Band attention -> att (tiled bf16 hi/lo)
    {
        dim3 grid(SEQT / 64, NHEAD, BATCH);
        band_attn_kernel<<<grid, 256, ATT_SMEM>>>(qkv, radius, atth, attl);
    }

    // 3) Output projection: [8192,512] x [512,512]^T -> out fp32
    {
        dim3 grid(DMODEL / 128, MROWS / 128);
        tc_gemm_bf16<<<grid, 128, GEMM_SMEM_TOTAL>>>(
            atth, attl, woh, wol, b_out, out, MROWS, DMODEL, DMODEL);
    }
}

// round 11
// speedup vs baseline: 1.2776x; 1.2094x over previous
#include <cuda_runtime.h>
#include <cuda_bf16.h>
#include <cstdint>

// Problem constants
#define BATCH 4
#define SEQT  2048
#define DMODEL 512
#define NHEAD 8
#define HD    64
#define THREE_D (3 * DMODEL)
#define MROWS (BATCH * SEQT)        // 8192

// Arch-feature dispatch: tcgen05/bulk-async only on *a targets.
#if !defined(__CUDA_ARCH__)
#  define TC_PATH 1
#elif defined(__CUDA_ARCH_HAS_FEATURE__) && \
      (__CUDA_ARCH_HAS_FEATURE__(SM103_ALL) || __CUDA_ARCH_HAS_FEATURE__(SM100_ALL))
#  define TC_PATH 1
#else
#  define TC_PATH 0
#endif

// ---------------------------------------------------------------------------
// Tiled+swizzled bf16 operand layout (SW64), TR=128 rows per tile:
//   tile (rblk, kblk) is contiguous 128*64 bytes (8KB) at
//     ((rblk * (K/32) + kblk) << 13)
//   within tile: row r, col c (bf16): bo = r*64 + c*2, swizzled bo^=((bo>>3)&0x30)
// ---------------------------------------------------------------------------

// Scratch (no cudaMalloc allowed)
__device__ float g_qkv[(size_t)MROWS * THREE_D];   // 48 MB fp32
__device__ alignas(128) __nv_bfloat16 g_xh[(size_t)MROWS * DMODEL];
__device__ alignas(128) __nv_bfloat16 g_xl[(size_t)MROWS * DMODEL];
__device__ alignas(128) __nv_bfloat16 g_wih[(size_t)THREE_D * DMODEL];
__device__ alignas(128) __nv_bfloat16 g_wil[(size_t)THREE_D * DMODEL];
__device__ alignas(128) __nv_bfloat16 g_woh[(size_t)DMODEL * DMODEL];
__device__ alignas(128) __nv_bfloat16 g_wol[(size_t)DMODEL * DMODEL];
__device__ alignas(128) __nv_bfloat16 g_atth[(size_t)MROWS * DMODEL];
__device__ alignas(128) __nv_bfloat16 g_attl[(size_t)MROWS * DMODEL];

// ===========================================================================
// Common helpers
// ===========================================================================
__device__ __forceinline__ uint32_t pack_bf16x2(__nv_bfloat16 a, __nv_bfloat16 b) {
    return (uint32_t)__bfloat16_as_ushort(a) |
           ((uint32_t)__bfloat16_as_ushort(b) << 16);
}

__device__ __forceinline__ void split_hilo(float v, __nv_bfloat16& h, __nv_bfloat16& l) {
    h = __float2bfloat16(v);
    l = __float2bfloat16(v - __bfloat162float(h));
}

__device__ __forceinline__ uint32_t sw64(uint32_t bo) {
    return bo ^ ((bo >> 3) & 0x30);
}

// tiled element load (fallback path only), TR=128
__device__ __forceinline__ float ld_tiled(
    const __nv_bfloat16* base, int row, int col, int Kdim)
{
    int kblk = col >> 5, cin = col & 31;
    int rblk = row >> 7, rin = row & 127;
    size_t tile = ((size_t)(rblk * (Kdim >> 5) + kblk)) << 13;
    uint32_t bo = sw64((uint32_t)(rin * 64 + cin * 2));
    return __bfloat162float(*(const __nv_bfloat16*)((const char*)base + tile + bo));
}

// ===========================================================================
// fp32 row-major -> tiled+swizzled bf16 hi/lo (TR=128). 8 elems/thread.
// ===========================================================================
__global__ __launch_bounds__(256) void cvt_tiled_kernel(
    const float* __restrict__ src,
    __nv_bfloat16* __restrict__ dh, __nv_bfloat16* __restrict__ dl,
    int R, int Kdim)
{
    int i = blockIdx.x * blockDim.x + threadIdx.x;   // 8-elem granule
    int n8 = (R * Kdim) >> 3;
    if (i >= n8) return;
    const int K8 = Kdim >> 3;
    int row = i / K8;
    int c8  = i - row * K8;

    float4 v0 = __ldg((const float4*)src + i * 2);
    float4 v1 = __ldg((const float4*)src + i * 2 + 1);

    __nv_bfloat16 h0,l0,h1,l1,h2,l2,h3,l3,h4,l4,h5,l5,h6,l6,h7,l7;
    split_hilo(v0.x,h0,l0); split_hilo(v0.y,h1,l1);
    split_hilo(v0.z,h2,l2); split_hilo(v0.w,h3,l3);
    split_hilo(v1.x,h4,l4); split_hilo(v1.y,h5,l5);
    split_hilo(v1.z,h6,l6); split_hilo(v1.w,h7,l7);
    uint4 hi, lo;
    hi.x = pack_bf16x2(h0,h1); hi.y = pack_bf16x2(h2,h3);
    hi.z = pack_bf16x2(h4,h5); hi.w = pack_bf16x2(h6,h7);
    lo.x = pack_bf16x2(l0,l1); lo.y = pack_bf16x2(l2,l3);
    lo.z = pack_bf16x2(l4,l5); lo.w = pack_bf16x2(l6,l7);

    int kblk = c8 >> 2, cc = c8 & 3;
    int rblk = row >> 7, rin = row & 127;
    size_t tile = ((size_t)(rblk * (Kdim >> 5) + kblk)) << 13;
    uint32_t bo = sw64((uint32_t)(rin * 64 + cc * 16));
    *(uint4*)((char*)dh + tile + bo) = hi;
    *(uint4*)((char*)dl + tile + bo) = lo;
}

// ===========================================================================
// tcgen05 + bulk-async PTX helpers (feature-gated)
// ===========================================================================
#if TC_PATH
__device__ __forceinline__ uint32_t smem_u32(const void* p) {
    uint32_t a;
    asm("{ .reg .u64 t; cvta.to.shared.u64 t, %1; cvt.u32.u64 %0, t; }"
        : "=r"(a) : "l"(p));
    return a;
}

#define TCGEN05_ALLOC(smem_result_addr, nCols) \
    asm volatile( \
        "tcgen05.alloc.cta_group::1.sync.aligned.shared::cta.b32 [%0], %1;" \
        :: "r"((uint32_t)(smem_result_addr)), "r"((uint32_t)(nCols)) : "memory")

#define TCGEN05_DEALLOC(tmem_addr, nCols) \
    asm volatile( \
        "tcgen05.dealloc.cta_group::1.sync.aligned.b32 %0, %1;" \
        :: "r"(tmem_addr), "r"((uint32_t)(nCols)))

#define TCGEN05_RELINQUISH_ALLOC_PERMIT() \
    asm volatile("tcgen05.relinquish_alloc_permit.cta_group::1.sync.aligned;")

#define TCGEN05_COMMIT(mbar_smem_addr) \
    asm volatile( \
        "tcgen05.commit.cta_group::1.mbarrier::arrive::one.shared::cluster.b64 [%0];" \
        :: "r"((uint32_t)(mbar_smem_addr)) : "memory")

#define TCGEN05_FENCE_AFTER() \
    asm volatile("tcgen05.fence::after_thread_sync;" ::: "memory")

#define TCGEN05_WAIT_LD() \
    asm volatile("tcgen05.wait::ld.sync.aligned;" ::: "memory")

#define MBARRIER_INIT(mbar_smem_addr, count) \
    asm volatile( \
        "mbarrier.init.shared.b64 [%0], %1;" \
        :: "r"((uint32_t)(mbar_smem_addr)), "r"((uint32_t)(count)) : "memory")

#define MBARRIER_EXPECT_TX(mbar_smem_addr, tx_bytes) \
    asm volatile( \
        "mbarrier.arrive.expect_tx.shared.b64 _, [%0], %1;" \
        :: "r"((uint32_t)(mbar_smem_addr)), "r"((uint32_t)(tx_bytes)) : "memory")

#define MBARRIER_WAIT_PARITY(mbar_smem_addr, phase_parity) do { \
    uint32_t _mbar = (uint32_t)(mbar_smem_addr); \
    uint32_t _parity = (uint32_t)(phase_parity); \
    uint32_t _done; \
    asm volatile( \
        "{\n\t.reg .pred p;\n\t" \
        "mbarrier.try_wait.parity.acquire.cta.shared::cta.b64 p, [%1], %2;\n\t" \
        "selp.b32 %0, 1, 0, p;\n\t}" \
        : "=r"(_done) : "r"(_mbar), "r"(_parity) : "memory"); \
    if (!_done) { \
        asm volatile( \
            "{\n\t.reg .pred P1;\n\t" \
            "WAIT_LOOP_%=:\n\t" \
            "mbarrier.try_wait.parity.acquire.cta.shared::cta.b64 P1, [%0], %1, 0x989680;\n\t" \
            "@P1 bra.uni WAIT_DONE_%=;\n\t" \
            "bra.uni WAIT_LOOP_%=;\n\t" \
            "WAIT_DONE_%=:\n\t}" \
            :: "r"(_mbar), "r"(_parity) : "memory"); \
    } \
} while(0)

// bulk async copy GMEM -> SMEM with mbarrier complete_tx
#define BULK_G2S(dst_smem, src_gmem, nbytes, mbar) \
    asm volatile( \
        "cp.async.bulk.shared::cluster.global.mbarrier::complete_tx::bytes " \
        "[%0], [%1], %2, [%3];" \
        :: "r"((uint32_t)(dst_smem)), "l"(src_gmem), "r"((uint32_t)(nbytes)), \
           "r"((uint32_t)(mbar)) : "memory")

#define TCGEN05_LD_32X32B_X32(r, tmem_addr) \
    asm volatile( \
        "tcgen05.ld.sync.aligned.32x32b.x32.b32 " \
        "{%0, %1, %2, %3, %4, %5, %6, %7, " \
        " %8, %9, %10, %11, %12, %13, %14, %15, " \
        " %16, %17, %18, %19, %20, %21, %22, %23, " \
        " %24, %25, %26, %27, %28, %29, %30, %31}, [%32];" \
        : "=r"((r)[0]),  "=r"((r)[1]),  "=r"((r)[2]),  "=r"((r)[3]), \
          "=r"((r)[4]),  "=r"((r)[5]),  "=r"((r)[6]),  "=r"((r)[7]), \
          "=r"((r)[8]),  "=r"((r)[9]),  "=r"((r)[10]), "=r"((r)[11]), \
          "=r"((r)[12]), "=r"((r)[13]), "=r"((r)[14]), "=r"((r)[15]), \
          "=r"((r)[16]), "=r"((r)[17]), "=r"((r)[18]), "=r"((r)[19]), \
          "=r"((r)[20]), "=r"((r)[21]), "=r"((r)[22]), "=r"((r)[23]), \
          "=r"((r)[24]), "=r"((r)[25]), "=r"((r)[26]), "=r"((r)[27]), \
          "=r"((r)[28]), "=r"((r)[29]), "=r"((r)[30]), "=r"((r)[31]) \
        : "r"(tmem_addr))

// SW64 descriptor: layout=4, version=1, SBO=32 (512B atom), LBO=1 (16B)
static constexpr uint64_t SMEM_DESC_BASE_SW64 =
    (uint64_t(4)  << 61) | (uint64_t(1) << 46) |
    (uint64_t(32) << 32) | (uint64_t(1) << 16);
#define MAKE_SMEM_DESC_SW64(base_addr) \
    (SMEM_DESC_BASE_SW64 | ((uint64_t)((base_addr) >> 4) & 0x3FFF))

__device__ __forceinline__ void mma_f16_ss_cg1(
    uint32_t d_tmem, uint64_t a_desc, uint64_t b_desc,
    uint32_t idesc, uint32_t enable)
{
    asm volatile(
        "{\n\t.reg .pred p;\n\t"
        "setp.ne.u32 p, %4, 0;\n\t"
        "tcgen05.mma.cta_group::1.kind::f16 [%0], %1, %2, %3, "
        "{%5, %5, %5, %5}, p;\n\t}"
        :: "r"(d_tmem), "l"(a_desc), "l"(b_desc), "r"(idesc),
           "r"(enable), "r"(0u)
        : "memory");
}

#define GEMM_IDESC ((1u<<4)|(1u<<7)|(1u<<10)|(16u<<17)|(8u<<24))  // M128 N128 bf16 f32acc
#endif // TC_PATH

// SMEM: header 1KB + 3 stages x (Ah 8K | Al 8K | Bh 8K | Bl 8K) = 97KB
#define STAGE_BYTES 32768
#define NPIPE 3
#define GEMM_SMEM_TOTAL (1024 + NPIPE * STAGE_BYTES)

// ===========================================================================
// GEMM (unchanged from R10): 128x128 tile, 3-stage warp-specialized pipeline
// ===========================================================================
__global__ __launch_bounds__(128, 2) void tc_gemm_bf16(
    const __nv_bfloat16* __restrict__ Ah, const __nv_bfloat16* __restrict__ Al,
    const __nv_bfloat16* __restrict__ Bh, const __nv_bfloat16* __restrict__ Bl,
    const float* __restrict__ bias, float* __restrict__ C,
    int M, int N, int K)
{
    extern __shared__ char smem[];
    const int tid = threadIdx.x;
    const int bm = blockIdx.y * 128;
    const int bn = blockIdx.x * 128;

#if TC_PATH
    const uint32_t smem_base = smem_u32(smem);
    const int wid  = tid >> 5;
    const int lane = tid & 31;

#define FULLB(b) (smem_base + 8  + 16 * (b))
#define EMPTB(b) (smem_base + 16 + 16 * (b))

    if (wid == 0) {
        TCGEN05_ALLOC(smem_base, 128);
        TCGEN05_RELINQUISH_ALLOC_PERMIT();
        if (lane == 0) {
#pragma unroll
            for (int b = 0; b < NPIPE; b++) {
                MBARRIER_INIT(FULLB(b), 1);
                MBARRIER_INIT(EMPTB(b), 1);
            }
        }
    }
    __syncthreads();
    uint32_t tmem;
    asm volatile("ld.shared.b32 %0, [%1];" : "=r"(tmem) : "r"(smem_base));

    const int nstage = K >> 5;
    const int nkblk  = K >> 5;

    if (tid == 32) {
        const size_t arow = (size_t)(bm >> 7) * nkblk;
        const size_t brow = (size_t)(bn >> 7) * nkblk;
        int eph[NPIPE] = {0, 0, 0};
        int buf = 0;
        for (int s = 0; s < nstage; s++) {
            const uint32_t OFF = smem_base + 1024 + buf * STAGE_BYTES;
            if (s >= NPIPE) { MBARRIER_WAIT_PARITY(EMPTB(buf), eph[buf]); eph[buf] ^= 1; }
            MBARRIER_EXPECT_TX(FULLB(buf), STAGE_BYTES);
            BULK_G2S(OFF,         (const char*)Ah + ((arow + s) << 13), 8192, FULLB(buf));
            BULK_G2S(OFF +  8192, (const char*)Al + ((arow + s) << 13), 8192, FULLB(buf));
            BULK_G2S(OFF + 16384, (const char*)Bh + ((brow + s) << 13), 8192, FULLB(buf));
            BULK_G2S(OFF + 24576, (const char*)Bl + ((brow + s) << 13), 8192, FULLB(buf));
            if (++buf == NPIPE) buf = 0;
        }
#pragma unroll
        for (int b = 0; b < NPIPE; b++)
            MBARRIER_WAIT_PARITY(EMPTB(b), eph[b]);
    }
    if (tid == 0) {
        int fph[NPIPE] = {0, 0, 0};
        int buf = 0;
        for (int s = 0; s < nstage; s++) {
            const uint32_t OFF = smem_base + 1024 + buf * STAGE_BYTES;

            MBARRIER_WAIT_PARITY(FULLB(buf), fph[buf]); fph[buf] ^= 1;

            uint64_t ah = MAKE_SMEM_DESC_SW64(OFF);
            uint64_t al = MAKE_SMEM_DESC_SW64(OFF + 8192);
            uint64_t bh = MAKE_SMEM_DESC_SW64(OFF + 16384);
            uint64_t bl = MAKE_SMEM_DESC_SW64(OFF + 24576);
#pragma unroll
            for (int kk = 0; kk < 2; kk++) {
                uint32_t en = (s > 0 || kk > 0) ? 1u : 0u;
                mma_f16_ss_cg1(tmem, ah + kk*2, bh + kk*2, GEMM_IDESC, en);
                mma_f16_ss_cg1(tmem, ah + kk*2, bl + kk*2, GEMM_IDESC, 1u);
                mma_f16_ss_cg1(tmem, al + kk*2, bh + kk*2, GEMM_IDESC, 1u);
            }
            TCGEN05_COMMIT(EMPTB(buf));
            if (++buf == NPIPE) buf = 0;
        }
    }
    __syncthreads();
    TCGEN05_FENCE_AFTER();

    {
        const int rowo = bm + wid * 32 + lane;
#pragma unroll
        for (int cb = 0; cb < 128; cb += 32) {
            uint32_t d[32];
            TCGEN05_LD_32X32B_X32(d, tmem + cb);
            TCGEN05_WAIT_LD();
            float* crow = C + (size_t)rowo * N + bn + cb;
#pragma unroll
            for (int g = 0; g < 8; g++) {
                float4 bb = __ldg((const float4*)(bias + bn + cb + g * 4));
                float4 o;
                o.x = __uint_as_float(d[g*4+0]) + bb.x;
                o.y = __uint_as_float(d[g*4+1]) + bb.y;
                o.z = __uint_as_float(d[g*4+2]) + bb.z;
                o.w = __uint_as_float(d[g*4+3]) + bb.w;
                *(float4*)(crow + g * 4) = o;
            }
        }
    }
    __syncthreads();
    if (wid == 0) {
        TCGEN05_DEALLOC(tmem, 128);
    }
#undef FULLB
#undef EMPTB

#else
    // ---------------- FFMA fallback: 128x128 tile via tiled loads ----------
    float* As = (float*)smem;
    float* Bs = (float*)(smem + 4096);

    const int trow = tid >> 4;
    const int tcol = tid & 15;
    float acc[16][8];
#pragma unroll
    for (int i = 0; i < 16; i++)
#pragma unroll
        for (int j = 0; j < 8; j++) acc[i][j] = 0.0f;

    for (int k0 = 0; k0 < K; k0 += 8) {
        for (int idx = tid; idx < 8 * 128; idx += 128) {
            int kk = idx >> 7, rr = idx & 127;
            As[kk * 128 + rr] =
                ld_tiled(Ah, bm + rr, k0 + kk, K) +
                ld_tiled(Al, bm + rr, k0 + kk, K);
            Bs[kk * 128 + rr] =
                ld_tiled(Bh, bn + rr, k0 + kk, K) +
                ld_tiled(Bl, bn + rr, k0 + kk, K);
        }
        __syncthreads();
#pragma unroll
        for (int kk = 0; kk < 8; kk++) {
            float a[16], b[8];
#pragma unroll
            for (int e = 0; e < 16; e++) a[e] = As[kk * 128 + trow * 16 + e];
#pragma unroll
            for (int e = 0; e < 8; e++)  b[e] = Bs[kk * 128 + tcol * 8 + e];
#pragma unroll
            for (int i = 0; i < 16; i++)
#pragma unroll
                for (int j = 0; j < 8; j++)
                    acc[i][j] += a[i] * b[j];
        }
        __syncthreads();
    }
    const int cn = bn + tcol * 8;
#pragma unroll
    for (int i = 0; i < 16; i++) {
        const int row = bm + trow * 16 + i;
#pragma unroll
        for (int j = 0; j < 8; j++)
            C[(size_t)row * N + cn + j] = acc[i][j] + bias[cn + j];
    }
#endif
}

// ===========================================================================
// Band attention v2: ONE THREAD = ONE QUERY. Zero shuffles.
// Block = 64 queries x (h,b), 64 threads. Q + 64-dim accumulator in
// registers; online softmax over the thread's own [q-R, q+R] window.
// K/V tile in SMEM with PAD=68 (8-lane LDS.128 phases cover all 32 banks).
// Writes att in tiled+swizzled bf16 hi/lo (TR=128).
// ===========================================================================
#define ATT_PAD 68
#define ATT_SMEM (2 * 96 * ATT_PAD * 4)   // 52.2 KB

__global__ __launch_bounds__(64) void band_attn_kernel(
    const float* __restrict__ qkv, const float* __restrict__ radius,
    __nv_bfloat16* __restrict__ atth, __nv_bfloat16* __restrict__ attl)
{
    extern __shared__ float sm[];
    float* sK = sm;
    float* sV = sm + 96 * ATT_PAD;

    const int tid = threadIdx.x;          // 0..63
    const int q0 = blockIdx.x * 64;
    const int h  = blockIdx.y;
    const int b  = blockIdx.z;

    float rr = 16.0f / (1.0f + expf(-radius[h]));
    if (rr < 1.0f) rr = 1.0f;
    const int R = (int)floorf(rr);

    const int klo = max(0, q0 - R);
    const int khi = min(SEQT - 1, q0 + 63 + R);
    const int Wt  = khi - klo + 1;        // <= 96

    const float* base = qkv + (size_t)b * SEQT * THREE_D;

    // Load K/V tile (coalesced float4, 64 threads)
    for (int i = tid; i < Wt * 16; i += 64) {
        int row = i >> 4;
        int c4  = (i & 15) * 4;
        const float* kr = base + (size_t)(klo + row) * THREE_D + DMODEL + h * HD + c4;
        *(float4*)&sK[row * ATT_PAD + c4] = __ldg((const float4*)kr);
        *(float4*)&sV[row * ATT_PAD + c4] = __ldg((const float4*)(kr + DMODEL));
    }

    const int q = q0 + tid;

    // Q row into registers (16 float4 from global; L2-resident)
    float qv[64];
    {
        const float* qrow = base + (size_t)q * THREE_D + h * HD;
#pragma unroll
        for (int g = 0; g < 16; g++) {
            float4 v = __ldg((const float4*)(qrow + g * 4));
            qv[g*4+0] = v.x; qv[g*4+1] = v.y; qv[g*4+2] = v.z; qv[g*4+3] = v.w;
        }
    }

    const int ks = max(0, q - R);
    const int ke = min(SEQT - 1, q + R);

    __syncthreads();

    // Online softmax over the window; acc[64] in registers
    float acc[64];
#pragma unroll
    for (int d = 0; d < 64; d++) acc[d] = 0.0f;
    float mrun = -3.402823466e38f;
    float ssum = 0.0f;

    for (int k = ks; k <= ke; k++) {
        const float* kr = &sK[(k - klo) * ATT_PAD];
        float s = 0.0f;
#pragma unroll
        for (int g = 0; g < 16; g++) {
            float4 kv = *(const float4*)(kr + g * 4);
            s += qv[g*4+0]*kv.x + qv[g*4+1]*kv.y + qv[g*4+2]*kv.z + qv[g*4+3]*kv.w;
        }
        s *= 0.125f;

        float mnew  = fmaxf(mrun, s);
        float scale = __expf(mrun - mnew);   // first iter: exp(-inf)=0
        float e     = __expf(s - mnew);
        ssum = ssum * scale + e;

        const float* vr = &sV[(k - klo) * ATT_PAD];
#pragma unroll
        for (int g = 0; g < 16; g++) {
            float4 vv = *(const float4*)(vr + g * 4);
            acc[g*4+0] = acc[g*4+0] * scale + e * vv.x;
            acc[g*4+1] = acc[g*4+1] * scale + e * vv.y;
            acc[g*4+2] = acc[g*4+2] * scale + e * vv.z;
            acc[g*4+3] = acc[g*4+3] * scale + e * vv.w;
        }
        mrun = mnew;
    }

    const float inv = 1.0f / ssum;

    // Write att row in tiled+swizzled hi/lo layout (TR=128)
    const int row = b * SEQT + q;
    const int rblk = row >> 7, rin = row & 127;
#pragma unroll
    for (int g = 0; g < 8; g++) {
        const int col8 = h * 8 + g;
        const int kblk = col8 >> 2, cc = col8 & 3;
        size_t tile = ((size_t)(rblk * 16 + kblk)) << 13;
        uint32_t bo = sw64((uint32_t)(rin * 64 + cc * 16));
        uint4 hi, lo;
        uint32_t* ph = (uint32_t*)&hi;
        uint32_t* pl = (uint32_t*)&lo;
#pragma unroll
        for (int p = 0; p < 4; p++) {
            float o0 = acc[g*8 + p*2]     * inv;
            float o1 = acc[g*8 + p*2 + 1] * inv;
            __nv_bfloat16 h0, l0, h1, l1;
            split_hilo(o0, h0, l0);
            split_hilo(o1, h1, l1);
            ph[p] = pack_bf16x2(h0, h1);
            pl[p] = pack_bf16x2(l0, l1);
        }
        *(uint4*)((char*)atth + tile + bo) = hi;
        *(uint4*)((char*)attl + tile + bo) = lo;
    }
}

// ---------------------------------------------------------------------------
extern "C" void kernel_launch(void* const* d_in, const int* in_sizes, int n_in,
                              void* d_out, int out_size)
{
    const float* x      = (const float*)d_in[0];
    const float* radius = (const float*)d_in[1];
    const float* w_in   = (const float*)d_in[2];
    const float* b_in   = (const float*)d_in[3];
    const float* w_out  = (const float*)d_in[4];
    const float* b_out  = (const float*)d_in[5];
    float* out = (float*)d_out;

    float *qkv;
    __nv_bfloat16 *xh, *xl, *wih, *wil, *woh, *wol, *atth, *attl;
    cudaGetSymbolAddress((void**)&qkv,  g_qkv);
    cudaGetSymbolAddress((void**)&xh,   g_xh);
    cudaGetSymbolAddress((void**)&xl,   g_xl);
    cudaGetSymbolAddress((void**)&wih,  g_wih);
    cudaGetSymbolAddress((void**)&wil,  g_wil);
    cudaGetSymbolAddress((void**)&woh,  g_woh);
    cudaGetSymbolAddress((void**)&wol,  g_wol);
    cudaGetSymbolAddress((void**)&atth, g_atth);
    cudaGetSymbolAddress((void**)&attl, g_attl);

    cudaFuncSetAttribute(tc_gemm_bf16,
                         cudaFuncAttributeMaxDynamicSharedMemorySize,
                         GEMM_SMEM_TOTAL);
    cudaFuncSetAttribute(band_attn_kernel,
                         cudaFuncAttributeMaxDynamicSharedMemorySize,
                         ATT_SMEM);

    // 0) fp32 -> tiled+swizzled bf16 hi/lo (all TR=128)
    {
        int n8;
        n8 = (MROWS * DMODEL) / 8;
        cvt_tiled_kernel<<<(n8 + 255) / 256, 256>>>(x, xh, xl, MROWS, DMODEL);
        n8 = (THREE_D * DMODEL) / 8;
        cvt_tiled_kernel<<<(n8 + 255) / 256, 256>>>(w_in, wih, wil, THREE_D, DMODEL);
        n8 = (DMODEL * DMODEL) / 8;
        cvt_tiled_kernel<<<(n8 + 255) / 256, 256>>>(w_out, woh, wol, DMODEL, DMODEL);
    }

    // 1) QKV projection: [8192,512] x [1536,512]^T -> [8192,1536] fp32
    {
        dim3 grid(THREE_D / 128, MROWS / 128);
        tc_gemm_bf16<<<grid, 128, GEMM_SMEM_TOTAL>>>(
            xh, xl, wih, wil, b_in, qkv, MROWS, THREE_D, DMODEL);
    }

    // 2) Band attention -> att (tiled bf16 hi/lo)
    {
        dim3 grid(SEQT / 64, NHEAD, BATCH);
        band_attn_kernel<<<grid, 64, ATT_SMEM>>>(qkv, radius, atth, attl);
    }

    // 3) Output projection: [8192,512] x [512,512]^T -> out fp32
    {
        dim3 grid(DMODEL / 128, MROWS / 128);
        tc_gemm_bf16<<<grid, 128, GEMM_SMEM_TOTAL>>>(
            atth, attl, woh, wol, b_out, out, MROWS, DMODEL, DMODEL);
    }
}